// round 1
// baseline (speedup 1.0000x reference)
#include <cuda_runtime.h>
#include <math.h>

#define BATCH 4
#define TSEQ  2048
#define CDIM  1024
#define NH    16
#define HD    64
#define BT    (BATCH * TSEQ)

// Scratch (allocation-free rule: __device__ globals)
__device__ float g_qkv[(size_t)BT * 3 * CDIM];   // [B*T, 3C]
__device__ float g_att[(size_t)BT * CDIM];       // [B*T, C] attention output

// ---------------------------------------------------------------------------
// NT GEMM: C[m,n] = sum_k A[m,k] * B[n,k] + bias[n]
// A: MxK row-major, B: NxK row-major (both K-contiguous), C: MxN row-major.
// BM=BN=64, BK=32, 256 threads, 4x4 per thread.
// ---------------------------------------------------------------------------
#define GBM 64
#define GBN 64
#define GBK 32

__global__ __launch_bounds__(256) void gemm_nt_kernel(
    const float* __restrict__ A, const float* __restrict__ B,
    const float* __restrict__ bias, float* __restrict__ C,
    int M, int N, int K)
{
    __shared__ float As[GBK][GBM + 4];   // transposed: As[k][m]
    __shared__ float Bs[GBK][GBN + 4];   // transposed: Bs[k][n]

    const int tid = threadIdx.x;
    const int tx = tid & 15;
    const int ty = tid >> 4;
    const int m0 = blockIdx.y * GBM;
    const int n0 = blockIdx.x * GBN;

    const float* Ag = A + (size_t)m0 * K;
    const float* Bg = B + (size_t)n0 * K;

    float acc[4][4] = {};

    for (int k0 = 0; k0 < K; k0 += GBK) {
        // 64 rows x 32 k-floats = 512 float4 per tile per matrix; 256 thr x 2
        #pragma unroll
        for (int it = 0; it < 2; it++) {
            int idx = tid + it * 256;
            int row = idx >> 3;
            int k4  = (idx & 7) * 4;
            float4 va = *(const float4*)&Ag[(size_t)row * K + k0 + k4];
            As[k4 + 0][row] = va.x; As[k4 + 1][row] = va.y;
            As[k4 + 2][row] = va.z; As[k4 + 3][row] = va.w;
            float4 vb = *(const float4*)&Bg[(size_t)row * K + k0 + k4];
            Bs[k4 + 0][row] = vb.x; Bs[k4 + 1][row] = vb.y;
            Bs[k4 + 2][row] = vb.z; Bs[k4 + 3][row] = vb.w;
        }
        __syncthreads();

        #pragma unroll
        for (int k = 0; k < GBK; k++) {
            float4 a4 = *(const float4*)&As[k][ty * 4];
            float4 b4 = *(const float4*)&Bs[k][tx * 4];
            float av[4] = {a4.x, a4.y, a4.z, a4.w};
            float bv[4] = {b4.x, b4.y, b4.z, b4.w};
            #pragma unroll
            for (int i = 0; i < 4; i++)
                #pragma unroll
                for (int j = 0; j < 4; j++)
                    acc[i][j] += av[i] * bv[j];
        }
        __syncthreads();
    }

    #pragma unroll
    for (int i = 0; i < 4; i++) {
        int m = m0 + ty * 4 + i;
        #pragma unroll
        for (int j = 0; j < 4; j++) {
            int n = n0 + tx * 4 + j;
            C[(size_t)m * N + n] = acc[i][j] + bias[n];
        }
    }
}

// ---------------------------------------------------------------------------
// Flash attention, fp32, causal. One block = one (batch, head, 64-query tile).
// Tiles of 64 keys; online softmax; 256 threads, 4x4 per thread for both the
// S = Q K^T and O += P V microkernels.
// smem: Qt [d][r] (transposed), Kt [d][c] (transposed), Vs [kk][d], Ps [r][kk]
// ---------------------------------------------------------------------------
#define FSP 68   // padded row stride (floats); 68*4B keeps float4 alignment

__global__ __launch_bounds__(256) void flash_kernel(
    const float* __restrict__ qkv, float* __restrict__ out)
{
    extern __shared__ float sm[];
    float* Qt = sm;
    float* Kt = sm + 64 * FSP;
    float* Vs = sm + 2 * 64 * FSP;
    float* Ps = sm + 3 * 64 * FSP;

    const int tid = threadIdx.x;
    const int tx = tid & 15;
    const int ty = tid >> 4;
    const int qt = blockIdx.x;   // query tile 0..31
    const int h  = blockIdx.y;
    const int b  = blockIdx.z;
    const int q0 = qt * 64;

    const size_t rstride = 3 * CDIM;
    const float* qbase = qkv + (size_t)(b * TSEQ) * rstride + h * HD;
    const float* kbase = qbase + CDIM;
    const float* vbase = qbase + 2 * CDIM;

    // Load Q tile transposed ([d][r]), pre-scaled by 1/sqrt(D)=0.125
    #pragma unroll
    for (int it = 0; it < 4; it++) {
        int idx = tid + it * 256;
        int row = idx >> 4;          // 0..63
        int d4  = (idx & 15) * 4;    // 0..60
        float4 v = *(const float4*)&qbase[(size_t)(q0 + row) * rstride + d4];
        Qt[(d4 + 0) * FSP + row] = v.x * 0.125f;
        Qt[(d4 + 1) * FSP + row] = v.y * 0.125f;
        Qt[(d4 + 2) * FSP + row] = v.z * 0.125f;
        Qt[(d4 + 3) * FSP + row] = v.w * 0.125f;
    }

    float m_i[4], l_i[4], o[4][4];
    #pragma unroll
    for (int i = 0; i < 4; i++) {
        m_i[i] = -1e30f; l_i[i] = 0.f;
        #pragma unroll
        for (int j = 0; j < 4; j++) o[i][j] = 0.f;
    }

    for (int kt = 0; kt <= qt; kt++) {
        const int k0 = kt * 64;
        __syncthreads();   // previous iter's Kt/Vs/Ps reads done (also fences Qt on iter 0)

        // Load K (transposed [d][c]) and V ([kk][d]) tiles
        #pragma unroll
        for (int it = 0; it < 4; it++) {
            int idx = tid + it * 256;
            int row = idx >> 4;
            int d4  = (idx & 15) * 4;
            float4 kv = *(const float4*)&kbase[(size_t)(k0 + row) * rstride + d4];
            Kt[(d4 + 0) * FSP + row] = kv.x;
            Kt[(d4 + 1) * FSP + row] = kv.y;
            Kt[(d4 + 2) * FSP + row] = kv.z;
            Kt[(d4 + 3) * FSP + row] = kv.w;
            float4 vv = *(const float4*)&vbase[(size_t)(k0 + row) * rstride + d4];
            *(float4*)&Vs[row * FSP + d4] = vv;
        }
        __syncthreads();

        // S[r][c] = sum_d Q[r][d]*K[c][d]
        float s[4][4] = {};
        #pragma unroll
        for (int d = 0; d < 64; d++) {
            float4 qa = *(const float4*)&Qt[d * FSP + ty * 4];
            float4 ka = *(const float4*)&Kt[d * FSP + tx * 4];
            float qv[4] = {qa.x, qa.y, qa.z, qa.w};
            float kv[4] = {ka.x, ka.y, ka.z, ka.w};
            #pragma unroll
            for (int i = 0; i < 4; i++)
                #pragma unroll
                for (int j = 0; j < 4; j++)
                    s[i][j] += qv[i] * kv[j];
        }

        // Causal mask (only the diagonal tile needs it; kt<qt tiles fully visible)
        if (kt == qt) {
            #pragma unroll
            for (int i = 0; i < 4; i++)
                #pragma unroll
                for (int j = 0; j < 4; j++)
                    if (k0 + tx * 4 + j > q0 + ty * 4 + i) s[i][j] = -1e30f;
        }

        // Online softmax update (row = 16 lanes sharing ty; xor-shuffle reduce)
        #pragma unroll
        for (int i = 0; i < 4; i++) {
            float mx = fmaxf(fmaxf(s[i][0], s[i][1]), fmaxf(s[i][2], s[i][3]));
            #pragma unroll
            for (int d = 8; d >= 1; d >>= 1)
                mx = fmaxf(mx, __shfl_xor_sync(0xffffffffu, mx, d));
            float m_new = fmaxf(m_i[i], mx);
            float corr  = __expf(m_i[i] - m_new);
            float sum = 0.f;
            #pragma unroll
            for (int j = 0; j < 4; j++) {
                s[i][j] = __expf(s[i][j] - m_new);
                sum += s[i][j];
            }
            #pragma unroll
            for (int d = 8; d >= 1; d >>= 1)
                sum += __shfl_xor_sync(0xffffffffu, sum, d);
            l_i[i] = l_i[i] * corr + sum;
            m_i[i] = m_new;
            #pragma unroll
            for (int j = 0; j < 4; j++) o[i][j] *= corr;
            *(float4*)&Ps[(ty * 4 + i) * FSP + tx * 4] =
                make_float4(s[i][0], s[i][1], s[i][2], s[i][3]);
        }
        __syncthreads();

        // O[r][d] += sum_kk P[r][kk] * V[kk][d]
        #pragma unroll
        for (int kk = 0; kk < 64; kk++) {
            float pv[4];
            #pragma unroll
            for (int i = 0; i < 4; i++) pv[i] = Ps[(ty * 4 + i) * FSP + kk];
            float4 vv = *(const float4*)&Vs[kk * FSP + tx * 4];
            float vvv[4] = {vv.x, vv.y, vv.z, vv.w};
            #pragma unroll
            for (int i = 0; i < 4; i++)
                #pragma unroll
                for (int j = 0; j < 4; j++)
                    o[i][j] += pv[i] * vvv[j];
        }
    }

    // Finalize: divide by l, write to [B,T,C] layout (head-major within C)
    #pragma unroll
    for (int i = 0; i < 4; i++) {
        float inv = 1.0f / l_i[i];
        int q = q0 + ty * 4 + i;
        float* orow = out + (size_t)(b * TSEQ + q) * CDIM + h * HD + tx * 4;
        *(float4*)orow = make_float4(o[i][0] * inv, o[i][1] * inv,
                                     o[i][2] * inv, o[i][3] * inv);
    }
}

// ---------------------------------------------------------------------------
// Launch
// ---------------------------------------------------------------------------
extern "C" void kernel_launch(void* const* d_in, const int* in_sizes, int n_in,
                              void* d_out, int out_size)
{
    const float* x      = (const float*)d_in[0];
    const float* W_qkv  = (const float*)d_in[1];
    const float* b_qkv  = (const float*)d_in[2];
    const float* W_proj = (const float*)d_in[3];
    const float* b_proj = (const float*)d_in[4];
    float* out = (float*)d_out;

    float *qkv, *att;
    cudaGetSymbolAddress((void**)&qkv, g_qkv);
    cudaGetSymbolAddress((void**)&att, g_att);

    dim3 blk(256);

    // 1) QKV projection: [8192,1024] x [3072,1024]^T
    gemm_nt_kernel<<<dim3((3 * CDIM) / GBN, BT / GBM), blk>>>(
        x, W_qkv, b_qkv, qkv, BT, 3 * CDIM, CDIM);

    // 2) Causal flash attention
    size_t smem = (size_t)4 * 64 * FSP * sizeof(float);   // 69632 B
    cudaFuncSetAttribute(flash_kernel,
                         cudaFuncAttributeMaxDynamicSharedMemorySize, (int)smem);
    flash_kernel<<<dim3(TSEQ / 64, NH, BATCH), blk, smem>>>(qkv, att);

    // 3) Output projection: [8192,1024] x [1024,1024]^T
    gemm_nt_kernel<<<dim3(CDIM / GBN, BT / GBM), blk>>>(
        att, W_proj, b_proj, out, BT, CDIM, CDIM);
}

// round 4
// speedup vs baseline: 1.7785x; 1.7785x over previous
#include <cuda_runtime.h>
#include <cuda_bf16.h>
#include <cstdint>
#include <math.h>

#define BATCH 4
#define TSEQ  2048
#define CDIM  1024
#define NH    16
#define HD    64
#define BT    (BATCH * TSEQ)
#define K3    (3 * CDIM)          // split-extended K dimension = 3072

// ---------------------------------------------------------------------------
// Scratch (__device__ globals; no allocation allowed)
// ---------------------------------------------------------------------------
__device__ float g_qkv[(size_t)BT * 3 * CDIM];             // [B*T, 3C] fp32
__device__ float g_att[(size_t)BT * CDIM];                 // [B*T, C]  fp32
__device__ __nv_bfloat16 g_xs[(size_t)BT * K3];            // x split  [hi|hi|lo]
__device__ __nv_bfloat16 g_as[(size_t)BT * K3];            // att split[hi|hi|lo]
__device__ __nv_bfloat16 g_wqs[(size_t)3 * CDIM * K3];     // W_qkv    [hi|lo|hi]
__device__ __nv_bfloat16 g_wps[(size_t)CDIM * K3];         // W_proj   [hi|lo|hi]

// ---------------------------------------------------------------------------
// PTX helpers (sm_100-baseline safe: cp.async + ldmatrix + mma.sync only)
// ---------------------------------------------------------------------------
__device__ __forceinline__ uint32_t smem_u32(const void* p) {
    uint32_t a;
    asm("{ .reg .u64 t; cvta.to.shared.u64 t, %1; cvt.u32.u64 %0, t; }"
        : "=r"(a) : "l"(p));
    return a;
}

#define CPASYNC16(dst, src) \
    asm volatile("cp.async.cg.shared.global [%0], [%1], 16;" \
        :: "r"(dst), "l"(src))
#define CPASYNC_COMMIT() asm volatile("cp.async.commit_group;")
#define CPASYNC_WAIT1()  asm volatile("cp.async.wait_group 1;")

#define LDSM_X4(r, addr) \
    asm volatile("ldmatrix.sync.aligned.m8n8.x4.shared.b16 {%0,%1,%2,%3}, [%4];" \
        : "=r"((r)[0]), "=r"((r)[1]), "=r"((r)[2]), "=r"((r)[3]) : "r"(addr))

#define MMA_BF16(d, a, br0, br1) \
    asm volatile("mma.sync.aligned.m16n8k16.row.col.f32.bf16.bf16.f32 " \
        "{%0,%1,%2,%3}, {%4,%5,%6,%7}, {%8,%9}, {%0,%1,%2,%3};" \
        : "+f"((d)[0]), "+f"((d)[1]), "+f"((d)[2]), "+f"((d)[3]) \
        : "r"((a)[0]), "r"((a)[1]), "r"((a)[2]), "r"((a)[3]), "r"(br0), "r"(br1))

// ---------------------------------------------------------------------------
// Split fp32 [R, 1024] -> bf16 [R, 3072]:
// A operand: hi @0, hi @1024, lo @2048   -> A' = [hi|hi|lo]
// B operand: hi @0, lo @1024, hi @2048   -> B' = [hi|lo|hi]
// A'.B'^T = hi.hi + hi.lo + lo.hi  (lo.lo term ~2^-18, dropped)
// ---------------------------------------------------------------------------
__global__ __launch_bounds__(256) void split_kernel(
    const float* __restrict__ src, __nv_bfloat16* __restrict__ dst,
    int hi2_off, int lo_off)
{
    int idx = blockIdx.x * blockDim.x + threadIdx.x;
    int row = idx >> 7;            // K/8 = 128 chunks per row
    int c8  = (idx & 127) << 3;

    const float* p = src + (size_t)row * CDIM + c8;
    float4 v0 = *(const float4*)p;
    float4 v1 = *(const float4*)(p + 4);
    float xs[8] = {v0.x, v0.y, v0.z, v0.w, v1.x, v1.y, v1.z, v1.w};

    unsigned short hs[8], ls[8];
    #pragma unroll
    for (int i = 0; i < 8; i++) {
        __nv_bfloat16 h = __float2bfloat16(xs[i]);
        float r = xs[i] - __bfloat162float(h);
        __nv_bfloat16 l = __float2bfloat16(r);
        hs[i] = *reinterpret_cast<unsigned short*>(&h);
        ls[i] = *reinterpret_cast<unsigned short*>(&l);
    }
    uint4 hv, lv;
    hv.x = (uint32_t)hs[0] | ((uint32_t)hs[1] << 16);
    hv.y = (uint32_t)hs[2] | ((uint32_t)hs[3] << 16);
    hv.z = (uint32_t)hs[4] | ((uint32_t)hs[5] << 16);
    hv.w = (uint32_t)hs[6] | ((uint32_t)hs[7] << 16);
    lv.x = (uint32_t)ls[0] | ((uint32_t)ls[1] << 16);
    lv.y = (uint32_t)ls[2] | ((uint32_t)ls[3] << 16);
    lv.z = (uint32_t)ls[4] | ((uint32_t)ls[5] << 16);
    lv.w = (uint32_t)ls[6] | ((uint32_t)ls[7] << 16);

    __nv_bfloat16* base = dst + (size_t)row * K3;
    *reinterpret_cast<uint4*>(base + c8)           = hv;
    *reinterpret_cast<uint4*>(base + hi2_off + c8) = hv;
    *reinterpret_cast<uint4*>(base + lo_off  + c8) = lv;
}

// ---------------------------------------------------------------------------
// bf16 NT GEMM via mma.sync (HMMA): C[m,n] = sum_k A[m,k]*B[n,k] + bias[n]
// A: [M, K'] row-major bf16, B: [N, K'] row-major bf16, C: [M, N] fp32.
// Tile 128x128, BK=64, 256 threads (8 warps as 2m x 4n, warp tile 64x32).
// Double-buffered cp.async, XOR-swizzled smem, ldmatrix.x4 operands.
// ---------------------------------------------------------------------------
#define GSTAGE 32768           // A 16KB + B 16KB per stage
#define GEMM_SMEM (2 * GSTAGE)

__global__ __launch_bounds__(256) void gemm_bf16_kernel(
    const __nv_bfloat16* __restrict__ A, const __nv_bfloat16* __restrict__ B,
    const float* __restrict__ bias, float* __restrict__ C,
    int M, int N, int K)
{
    extern __shared__ char sm[];
    uint32_t smb = smem_u32(sm);
    const int tid  = threadIdx.x;
    const int lane = tid & 31;
    const int wid  = tid >> 5;
    const int wm   = wid >> 2;        // 0..1
    const int wn   = wid & 3;         // 0..3
    const int m0   = blockIdx.y * 128;
    const int n0   = blockIdx.x * 128;
    const int NK   = K >> 6;          // 64-wide k stages

    const size_t Kb = (size_t)K * 2;  // row bytes
    const char* Abase = (const char*)A + (size_t)m0 * Kb;
    const char* Bbase = (const char*)B + (size_t)n0 * Kb;

    const int lr = tid >> 3;          // 0..31  (gmem load row)
    const int lc = (tid & 7) << 4;    // byte col 0..112

    float acc[4][4][4];
    #pragma unroll
    for (int i = 0; i < 4; i++)
        #pragma unroll
        for (int j = 0; j < 4; j++)
            #pragma unroll
            for (int r = 0; r < 4; r++) acc[i][j][r] = 0.f;

    // ldmatrix per-thread row offsets (swizzle XOR depends on row only)
    const int lrow  = lane & 15;
    const int lhalf = (lane >> 4) << 4;   // 0 or 16 bytes
    uint32_t arow[4], axor[4], brow[2], bxor[2];
    #pragma unroll
    for (int mi = 0; mi < 4; mi++) {
        int r = wm * 64 + mi * 16 + lrow;
        arow[mi] = r * 128; axor[mi] = (r & 7) << 4;
    }
    #pragma unroll
    for (int bi = 0; bi < 2; bi++) {
        int r = wn * 32 + bi * 16 + lrow;
        brow[bi] = r * 128; bxor[bi] = (r & 7) << 4;
    }

    auto load_stage = [&](int kt, int s) {
        uint32_t sa = smb + s * GSTAGE;
        uint32_t sb = sa + 16384;
        size_t ktb = (size_t)kt << 7;   // kt*128 bytes
        #pragma unroll
        for (int p = 0; p < 4; p++) {
            int row = lr + p * 32;
            uint32_t so = row * 128 + (lc ^ ((row & 7) << 4));
            CPASYNC16(sa + so, Abase + (size_t)row * Kb + ktb + lc);
            CPASYNC16(sb + so, Bbase + (size_t)row * Kb + ktb + lc);
        }
    };

    load_stage(0, 0); CPASYNC_COMMIT();
    load_stage(1, 1); CPASYNC_COMMIT();

    for (int kt = 0; kt < NK; kt++) {
        CPASYNC_WAIT1();
        __syncthreads();
        uint32_t sa = smb + (kt & 1) * GSTAGE;
        uint32_t sb = sa + 16384;

        #pragma unroll
        for (int ks = 0; ks < 4; ks++) {
            uint32_t kb = (ks << 5) + lhalf;
            uint32_t a[4][4], b[2][4];
            #pragma unroll
            for (int mi = 0; mi < 4; mi++)
                LDSM_X4(a[mi], sa + arow[mi] + (kb ^ axor[mi]));
            #pragma unroll
            for (int bi = 0; bi < 2; bi++)
                LDSM_X4(b[bi], sb + brow[bi] + (kb ^ bxor[bi]));
            #pragma unroll
            for (int mi = 0; mi < 4; mi++)
                #pragma unroll
                for (int ni = 0; ni < 4; ni++)
                    MMA_BF16(acc[mi][ni], a[mi],
                             b[ni >> 1][ni & 1], b[ni >> 1][(ni & 1) + 2]);
        }
        __syncthreads();
        if (kt + 2 < NK) load_stage(kt + 2, kt & 1);
        CPASYNC_COMMIT();
    }

    // Epilogue: + bias, fp32 stores
    const int g  = lane >> 2;
    const int tg = (lane & 3) << 1;
    #pragma unroll
    for (int mi = 0; mi < 4; mi++) {
        int r0 = m0 + wm * 64 + mi * 16 + g;
        #pragma unroll
        for (int ni = 0; ni < 4; ni++) {
            int col = n0 + wn * 32 + ni * 8 + tg;
            float b0 = bias[col], b1 = bias[col + 1];
            float2 v0 = {acc[mi][ni][0] + b0, acc[mi][ni][1] + b1};
            float2 v1 = {acc[mi][ni][2] + b0, acc[mi][ni][3] + b1};
            *(float2*)&C[(size_t)r0 * N + col] = v0;
            *(float2*)&C[(size_t)(r0 + 8) * N + col] = v1;
        }
    }
}

// ---------------------------------------------------------------------------
// Flash attention, fp32, causal (unchanged from Round-1 passing kernel)
// ---------------------------------------------------------------------------
#define FSP 68

__global__ __launch_bounds__(256) void flash_kernel(
    const float* __restrict__ qkv, float* __restrict__ out)
{
    extern __shared__ float smf[];
    float* Qt = smf;
    float* Kt = smf + 64 * FSP;
    float* Vs = smf + 2 * 64 * FSP;
    float* Ps = smf + 3 * 64 * FSP;

    const int tid = threadIdx.x;
    const int tx = tid & 15;
    const int ty = tid >> 4;
    const int qt = blockIdx.x;
    const int h  = blockIdx.y;
    const int b  = blockIdx.z;
    const int q0 = qt * 64;

    const size_t rstride = 3 * CDIM;
    const float* qbase = qkv + (size_t)(b * TSEQ) * rstride + h * HD;
    const float* kbase = qbase + CDIM;
    const float* vbase = qbase + 2 * CDIM;

    #pragma unroll
    for (int it = 0; it < 4; it++) {
        int idx = tid + it * 256;
        int row = idx >> 4;
        int d4  = (idx & 15) * 4;
        float4 v = *(const float4*)&qbase[(size_t)(q0 + row) * rstride + d4];
        Qt[(d4 + 0) * FSP + row] = v.x * 0.125f;
        Qt[(d4 + 1) * FSP + row] = v.y * 0.125f;
        Qt[(d4 + 2) * FSP + row] = v.z * 0.125f;
        Qt[(d4 + 3) * FSP + row] = v.w * 0.125f;
    }

    float m_i[4], l_i[4], o[4][4];
    #pragma unroll
    for (int i = 0; i < 4; i++) {
        m_i[i] = -1e30f; l_i[i] = 0.f;
        #pragma unroll
        for (int j = 0; j < 4; j++) o[i][j] = 0.f;
    }

    for (int kt = 0; kt <= qt; kt++) {
        const int k0 = kt * 64;
        __syncthreads();

        #pragma unroll
        for (int it = 0; it < 4; it++) {
            int idx = tid + it * 256;
            int row = idx >> 4;
            int d4  = (idx & 15) * 4;
            float4 kv = *(const float4*)&kbase[(size_t)(k0 + row) * rstride + d4];
            Kt[(d4 + 0) * FSP + row] = kv.x;
            Kt[(d4 + 1) * FSP + row] = kv.y;
            Kt[(d4 + 2) * FSP + row] = kv.z;
            Kt[(d4 + 3) * FSP + row] = kv.w;
            float4 vv = *(const float4*)&vbase[(size_t)(k0 + row) * rstride + d4];
            *(float4*)&Vs[row * FSP + d4] = vv;
        }
        __syncthreads();

        float s[4][4] = {};
        #pragma unroll
        for (int d = 0; d < 64; d++) {
            float4 qa = *(const float4*)&Qt[d * FSP + ty * 4];
            float4 ka = *(const float4*)&Kt[d * FSP + tx * 4];
            float qv[4] = {qa.x, qa.y, qa.z, qa.w};
            float kv[4] = {ka.x, ka.y, ka.z, ka.w};
            #pragma unroll
            for (int i = 0; i < 4; i++)
                #pragma unroll
                for (int j = 0; j < 4; j++)
                    s[i][j] += qv[i] * kv[j];
        }

        if (kt == qt) {
            #pragma unroll
            for (int i = 0; i < 4; i++)
                #pragma unroll
                for (int j = 0; j < 4; j++)
                    if (k0 + tx * 4 + j > q0 + ty * 4 + i) s[i][j] = -1e30f;
        }

        #pragma unroll
        for (int i = 0; i < 4; i++) {
            float mx = fmaxf(fmaxf(s[i][0], s[i][1]), fmaxf(s[i][2], s[i][3]));
            #pragma unroll
            for (int d = 8; d >= 1; d >>= 1)
                mx = fmaxf(mx, __shfl_xor_sync(0xffffffffu, mx, d));
            float m_new = fmaxf(m_i[i], mx);
            float corr  = __expf(m_i[i] - m_new);
            float sum = 0.f;
            #pragma unroll
            for (int j = 0; j < 4; j++) {
                s[i][j] = __expf(s[i][j] - m_new);
                sum += s[i][j];
            }
            #pragma unroll
            for (int d = 8; d >= 1; d >>= 1)
                sum += __shfl_xor_sync(0xffffffffu, sum, d);
            l_i[i] = l_i[i] * corr + sum;
            m_i[i] = m_new;
            #pragma unroll
            for (int j = 0; j < 4; j++) o[i][j] *= corr;
            *(float4*)&Ps[(ty * 4 + i) * FSP + tx * 4] =
                make_float4(s[i][0], s[i][1], s[i][2], s[i][3]);
        }
        __syncthreads();

        #pragma unroll
        for (int kk = 0; kk < 64; kk++) {
            float pv[4];
            #pragma unroll
            for (int i = 0; i < 4; i++) pv[i] = Ps[(ty * 4 + i) * FSP + kk];
            float4 vv = *(const float4*)&Vs[kk * FSP + tx * 4];
            float vvv[4] = {vv.x, vv.y, vv.z, vv.w};
            #pragma unroll
            for (int i = 0; i < 4; i++)
                #pragma unroll
                for (int j = 0; j < 4; j++)
                    o[i][j] += pv[i] * vvv[j];
        }
    }

    #pragma unroll
    for (int i = 0; i < 4; i++) {
        float inv = 1.0f / l_i[i];
        int q = q0 + ty * 4 + i;
        float* orow = out + (size_t)(b * TSEQ + q) * CDIM + h * HD + tx * 4;
        *(float4*)orow = make_float4(o[i][0] * inv, o[i][1] * inv,
                                     o[i][2] * inv, o[i][3] * inv);
    }
}

// ---------------------------------------------------------------------------
// Launch
// ---------------------------------------------------------------------------
extern "C" void kernel_launch(void* const* d_in, const int* in_sizes, int n_in,
                              void* d_out, int out_size)
{
    const float* x      = (const float*)d_in[0];
    const float* W_qkv  = (const float*)d_in[1];
    const float* b_qkv  = (const float*)d_in[2];
    const float* W_proj = (const float*)d_in[3];
    const float* b_proj = (const float*)d_in[4];
    float* out = (float*)d_out;

    float *qkv, *att;
    __nv_bfloat16 *xs, *as, *wqs, *wps;
    cudaGetSymbolAddress((void**)&qkv, g_qkv);
    cudaGetSymbolAddress((void**)&att, g_att);
    cudaGetSymbolAddress((void**)&xs,  g_xs);
    cudaGetSymbolAddress((void**)&as,  g_as);
    cudaGetSymbolAddress((void**)&wqs, g_wqs);
    cudaGetSymbolAddress((void**)&wps, g_wps);

    cudaFuncSetAttribute(gemm_bf16_kernel,
                         cudaFuncAttributeMaxDynamicSharedMemorySize, GEMM_SMEM);
    size_t fsmem = (size_t)4 * 64 * FSP * sizeof(float);
    cudaFuncSetAttribute(flash_kernel,
                         cudaFuncAttributeMaxDynamicSharedMemorySize, (int)fsmem);

    // Splits: A operands [hi|hi|lo], B operands [hi|lo|hi]
    split_kernel<<<BT * CDIM / 8 / 256, 256>>>(x, xs, CDIM, 2 * CDIM);
    split_kernel<<<3 * CDIM * CDIM / 8 / 256, 256>>>(W_qkv, wqs, 2 * CDIM, CDIM);
    split_kernel<<<CDIM * CDIM / 8 / 256, 256>>>(W_proj, wps, 2 * CDIM, CDIM);

    // 1) QKV projection: [8192,3072(K')] x [3072,3072(K')]^T -> fp32 [8192,3072]
    gemm_bf16_kernel<<<dim3(3 * CDIM / 128, BT / 128), 256, GEMM_SMEM>>>(
        xs, wqs, b_qkv, qkv, BT, 3 * CDIM, K3);

    // 2) Causal flash attention (fp32)
    flash_kernel<<<dim3(TSEQ / 64, NH, BATCH), 256, fsmem>>>(qkv, att);

    // 3) Output projection
    split_kernel<<<BT * CDIM / 8 / 256, 256>>>(att, as, CDIM, 2 * CDIM);
    gemm_bf16_kernel<<<dim3(CDIM / 128, BT / 128), 256, GEMM_SMEM>>>(
        as, wps, b_proj, out, BT, CDIM, K3);
}

// round 5
// speedup vs baseline: 2.5241x; 1.4193x over previous
#include <cuda_runtime.h>
#include <cuda_bf16.h>
#include <cstdint>
#include <math.h>

#define BATCH 4
#define TSEQ  2048
#define CDIM  1024
#define NH    16
#define HD    64
#define BT    (BATCH * TSEQ)
#define K3    (3 * CDIM)          // split-extended K dimension = 3072

// ---------------------------------------------------------------------------
// Scratch (__device__ globals; no allocation allowed)
// ---------------------------------------------------------------------------
__device__ float g_qkv[(size_t)BT * 3 * CDIM];             // [B*T, 3C] fp32
__device__ float g_att[(size_t)BT * CDIM];                 // [B*T, C]  fp32
__device__ __nv_bfloat16 g_xs[(size_t)BT * K3];            // x split  [hi|hi|lo]
__device__ __nv_bfloat16 g_as[(size_t)BT * K3];            // att split[hi|hi|lo]
__device__ __nv_bfloat16 g_wqs[(size_t)3 * CDIM * K3];     // W_qkv    [hi|lo|hi]
__device__ __nv_bfloat16 g_wps[(size_t)CDIM * K3];         // W_proj   [hi|lo|hi]

// ---------------------------------------------------------------------------
// PTX helpers (sm_100-baseline safe: cp.async + ldmatrix + mma.sync only)
// ---------------------------------------------------------------------------
__device__ __forceinline__ uint32_t smem_u32(const void* p) {
    uint32_t a;
    asm("{ .reg .u64 t; cvta.to.shared.u64 t, %1; cvt.u32.u64 %0, t; }"
        : "=r"(a) : "l"(p));
    return a;
}

#define CPASYNC16(dst, src) \
    asm volatile("cp.async.cg.shared.global [%0], [%1], 16;" \
        :: "r"(dst), "l"(src))
#define CPASYNC_COMMIT() asm volatile("cp.async.commit_group;")
#define CPASYNC_WAIT1()  asm volatile("cp.async.wait_group 1;")

#define LDSM_X4(r, addr) \
    asm volatile("ldmatrix.sync.aligned.m8n8.x4.shared.b16 {%0,%1,%2,%3}, [%4];" \
        : "=r"((r)[0]), "=r"((r)[1]), "=r"((r)[2]), "=r"((r)[3]) : "r"(addr))

#define LDSM_X4_T(r, addr) \
    asm volatile("ldmatrix.sync.aligned.m8n8.x4.trans.shared.b16 {%0,%1,%2,%3}, [%4];" \
        : "=r"((r)[0]), "=r"((r)[1]), "=r"((r)[2]), "=r"((r)[3]) : "r"(addr))

#define MMA_BF16(d, a, br0, br1) \
    asm volatile("mma.sync.aligned.m16n8k16.row.col.f32.bf16.bf16.f32 " \
        "{%0,%1,%2,%3}, {%4,%5,%6,%7}, {%8,%9}, {%0,%1,%2,%3};" \
        : "+f"((d)[0]), "+f"((d)[1]), "+f"((d)[2]), "+f"((d)[3]) \
        : "r"((a)[0]), "r"((a)[1]), "r"((a)[2]), "r"((a)[3]), "r"(br0), "r"(br1))

// pack two f32 -> bf16x2 (lo = x0, hi = x1)
#define PACK_BF16X2(res, x0, x1) \
    asm("cvt.rn.bf16x2.f32 %0, %1, %2;" : "=r"(res) : "f"(x1), "f"(x0))

// ---------------------------------------------------------------------------
// Split fp32 [R, 1024] -> bf16 [R, 3072]:
// A operand: hi @0, hi @1024, lo @2048   -> A' = [hi|hi|lo]
// B operand: hi @0, lo @1024, hi @2048   -> B' = [hi|lo|hi]
// A'.B'^T = hi.hi + hi.lo + lo.hi  (lo.lo term ~2^-18, dropped)
// ---------------------------------------------------------------------------
__global__ __launch_bounds__(256) void split_kernel(
    const float* __restrict__ src, __nv_bfloat16* __restrict__ dst,
    int hi2_off, int lo_off)
{
    int idx = blockIdx.x * blockDim.x + threadIdx.x;
    int row = idx >> 7;            // K/8 = 128 chunks per row
    int c8  = (idx & 127) << 3;

    const float* p = src + (size_t)row * CDIM + c8;
    float4 v0 = *(const float4*)p;
    float4 v1 = *(const float4*)(p + 4);
    float xs[8] = {v0.x, v0.y, v0.z, v0.w, v1.x, v1.y, v1.z, v1.w};

    uint32_t hv[4], lv[4];
    #pragma unroll
    for (int i = 0; i < 4; i++) {
        float x0 = xs[2*i], x1 = xs[2*i + 1];
        uint32_t ph; PACK_BF16X2(ph, x0, x1);
        float h0 = __uint_as_float(ph << 16);
        float h1 = __uint_as_float(ph & 0xffff0000u);
        uint32_t pl; PACK_BF16X2(pl, x0 - h0, x1 - h1);
        hv[i] = ph; lv[i] = pl;
    }
    uint4 hq = make_uint4(hv[0], hv[1], hv[2], hv[3]);
    uint4 lq = make_uint4(lv[0], lv[1], lv[2], lv[3]);

    __nv_bfloat16* base = dst + (size_t)row * K3;
    *reinterpret_cast<uint4*>(base + c8)           = hq;
    *reinterpret_cast<uint4*>(base + hi2_off + c8) = hq;
    *reinterpret_cast<uint4*>(base + lo_off  + c8) = lq;
}

// ---------------------------------------------------------------------------
// bf16 NT GEMM via mma.sync (HMMA) — unchanged from Round-4 passing kernel
// ---------------------------------------------------------------------------
#define GSTAGE 32768           // A 16KB + B 16KB per stage
#define GEMM_SMEM (2 * GSTAGE)

__global__ __launch_bounds__(256) void gemm_bf16_kernel(
    const __nv_bfloat16* __restrict__ A, const __nv_bfloat16* __restrict__ B,
    const float* __restrict__ bias, float* __restrict__ C,
    int M, int N, int K)
{
    extern __shared__ char sm[];
    uint32_t smb = smem_u32(sm);
    const int tid  = threadIdx.x;
    const int lane = tid & 31;
    const int wid  = tid >> 5;
    const int wm   = wid >> 2;
    const int wn   = wid & 3;
    const int m0   = blockIdx.y * 128;
    const int n0   = blockIdx.x * 128;
    const int NK   = K >> 6;

    const size_t Kb = (size_t)K * 2;
    const char* Abase = (const char*)A + (size_t)m0 * Kb;
    const char* Bbase = (const char*)B + (size_t)n0 * Kb;

    const int lr = tid >> 3;
    const int lc = (tid & 7) << 4;

    float acc[4][4][4];
    #pragma unroll
    for (int i = 0; i < 4; i++)
        #pragma unroll
        for (int j = 0; j < 4; j++)
            #pragma unroll
            for (int r = 0; r < 4; r++) acc[i][j][r] = 0.f;

    const int lrow  = lane & 15;
    const int lhalf = (lane >> 4) << 4;
    uint32_t arow[4], axor[4], brow[2], bxor[2];
    #pragma unroll
    for (int mi = 0; mi < 4; mi++) {
        int r = wm * 64 + mi * 16 + lrow;
        arow[mi] = r * 128; axor[mi] = (r & 7) << 4;
    }
    #pragma unroll
    for (int bi = 0; bi < 2; bi++) {
        int r = wn * 32 + bi * 16 + lrow;
        brow[bi] = r * 128; bxor[bi] = (r & 7) << 4;
    }

    auto load_stage = [&](int kt, int s) {
        uint32_t sa = smb + s * GSTAGE;
        uint32_t sb = sa + 16384;
        size_t ktb = (size_t)kt << 7;
        #pragma unroll
        for (int p = 0; p < 4; p++) {
            int row = lr + p * 32;
            uint32_t so = row * 128 + (lc ^ ((row & 7) << 4));
            CPASYNC16(sa + so, Abase + (size_t)row * Kb + ktb + lc);
            CPASYNC16(sb + so, Bbase + (size_t)row * Kb + ktb + lc);
        }
    };

    load_stage(0, 0); CPASYNC_COMMIT();
    load_stage(1, 1); CPASYNC_COMMIT();

    for (int kt = 0; kt < NK; kt++) {
        CPASYNC_WAIT1();
        __syncthreads();
        uint32_t sa = smb + (kt & 1) * GSTAGE;
        uint32_t sb = sa + 16384;

        #pragma unroll
        for (int ks = 0; ks < 4; ks++) {
            uint32_t kb = (ks << 5) + lhalf;
            uint32_t a[4][4], b[2][4];
            #pragma unroll
            for (int mi = 0; mi < 4; mi++)
                LDSM_X4(a[mi], sa + arow[mi] + (kb ^ axor[mi]));
            #pragma unroll
            for (int bi = 0; bi < 2; bi++)
                LDSM_X4(b[bi], sb + brow[bi] + (kb ^ bxor[bi]));
            #pragma unroll
            for (int mi = 0; mi < 4; mi++)
                #pragma unroll
                for (int ni = 0; ni < 4; ni++)
                    MMA_BF16(acc[mi][ni], a[mi],
                             b[ni >> 1][ni & 1], b[ni >> 1][(ni & 1) + 2]);
        }
        __syncthreads();
        if (kt + 2 < NK) load_stage(kt + 2, kt & 1);
        CPASYNC_COMMIT();
    }

    const int g  = lane >> 2;
    const int tg = (lane & 3) << 1;
    #pragma unroll
    for (int mi = 0; mi < 4; mi++) {
        int r0 = m0 + wm * 64 + mi * 16 + g;
        #pragma unroll
        for (int ni = 0; ni < 4; ni++) {
            int col = n0 + wn * 32 + ni * 8 + tg;
            float b0 = bias[col], b1 = bias[col + 1];
            float2 v0 = {acc[mi][ni][0] + b0, acc[mi][ni][1] + b1};
            float2 v1 = {acc[mi][ni][2] + b0, acc[mi][ni][3] + b1};
            *(float2*)&C[(size_t)r0 * N + col] = v0;
            *(float2*)&C[(size_t)(r0 + 8) * N + col] = v1;
        }
    }
}

// ---------------------------------------------------------------------------
// Flash attention via HMMA with bf16 hi/lo split, causal.
// CTA = 128 queries (8 warps x 16 rows), key tiles of 64, D = 64.
// S = QK^T: 3-combo split MMA (Qhi.Khi + Qhi.Klo + Qlo.Khi); scale 0.125
//   (power of 2) folded into Q before splitting -> exact.
// P.V: P fragments built in registers from S accumulators (FA-2 layout reuse),
//   split as Phi/Plo; V split in smem; 3-combo MMA with ldmatrix.trans.
// smem: Qhi/Qlo 16KB each (128 rows x 128B), Khi/Klo/Vhi/Vlo 8KB each = 64KB.
// ---------------------------------------------------------------------------
#define FLASH_SMEM 65536

__global__ __launch_bounds__(256, 1) void flash_hmma_kernel(
    const float* __restrict__ qkv, float* __restrict__ out)
{
    extern __shared__ char sm[];
    uint32_t smb = smem_u32(sm);
    const uint32_t sQh = smb;
    const uint32_t sQl = smb + 16384;
    const uint32_t sKh = smb + 32768;
    const uint32_t sKl = smb + 40960;
    const uint32_t sVh = smb + 49152;
    const uint32_t sVl = smb + 57344;
    char* Qh = sm;          char* Ql = sm + 16384;
    char* Kh = sm + 32768;  char* Kl = sm + 40960;
    char* Vh = sm + 49152;  char* Vl = sm + 57344;

    const int tid  = threadIdx.x;
    const int lane = tid & 31;
    const int w    = tid >> 5;
    const int g    = lane >> 2;
    const int t    = lane & 3;
    const int qt   = (gridDim.x - 1) - blockIdx.x;   // heavy tiles first
    const int h    = blockIdx.y;
    const int b    = blockIdx.z;
    const int q0   = qt * 128;

    const float* qbase = qkv + (size_t)(b * TSEQ) * 3072 + h * 64;

    // ---- Load Q tile (128 x 64 fp32), scale by 0.125, split hi/lo to smem ----
    for (int u = tid; u < 1024; u += 256) {
        int row = u >> 3;
        int c8  = (u & 7) * 8;
        const float* p = qbase + (size_t)(q0 + row) * 3072 + c8;
        float4 v0 = *(const float4*)p;
        float4 v1 = *(const float4*)(p + 4);
        float xs[8] = {v0.x, v0.y, v0.z, v0.w, v1.x, v1.y, v1.z, v1.w};
        uint32_t hv[4], lv[4];
        #pragma unroll
        for (int i = 0; i < 4; i++) {
            float x0 = xs[2*i] * 0.125f, x1 = xs[2*i + 1] * 0.125f;
            uint32_t ph; PACK_BF16X2(ph, x0, x1);
            float h0 = __uint_as_float(ph << 16);
            float h1 = __uint_as_float(ph & 0xffff0000u);
            uint32_t pl; PACK_BF16X2(pl, x0 - h0, x1 - h1);
            hv[i] = ph; lv[i] = pl;
        }
        uint32_t off = row * 128 + ((uint32_t)(c8 * 2) ^ ((row & 7) << 4));
        *(uint4*)(Qh + off) = make_uint4(hv[0], hv[1], hv[2], hv[3]);
        *(uint4*)(Ql + off) = make_uint4(lv[0], lv[1], lv[2], lv[3]);
    }

    // ---- per-warp ldmatrix addressing ----
    const int lrow  = lane & 15;
    const int lhalf = (lane >> 4) << 4;
    const uint32_t aoff = (uint32_t)((w * 16 + lrow) * 128);
    const uint32_t axor = (uint32_t)((lrow & 7) << 4);
    const uint32_t kxor = axor;

    // ---- accumulators ----
    float o[8][4];
    #pragma unroll
    for (int i = 0; i < 8; i++)
        #pragma unroll
        for (int j = 0; j < 4; j++) o[i][j] = 0.f;
    float m0 = -1e30f, m1 = -1e30f, l0 = 0.f, l1 = 0.f;
    const int qw = q0 + w * 16;     // warp's first query row

    const int nkt = 2 * qt + 2;
    for (int kt = 0; kt < nkt; kt++) {
        const int k0 = kt * 64;
        __syncthreads();

        // ---- Load K/V tiles (64 x 64 fp32 each), split hi/lo to smem ----
        for (int u = tid; u < 1024; u += 256) {
            int isV = u >> 9;
            int uu  = u & 511;
            int row = uu >> 3;
            int c8  = (uu & 7) * 8;
            const float* p = qbase + (size_t)(k0 + row) * 3072
                           + (isV ? 2048 : 1024) + c8;
            float4 v0 = *(const float4*)p;
            float4 v1 = *(const float4*)(p + 4);
            float xs[8] = {v0.x, v0.y, v0.z, v0.w, v1.x, v1.y, v1.z, v1.w};
            uint32_t hv[4], lv[4];
            #pragma unroll
            for (int i = 0; i < 4; i++) {
                float x0 = xs[2*i], x1 = xs[2*i + 1];
                uint32_t ph; PACK_BF16X2(ph, x0, x1);
                float h0 = __uint_as_float(ph << 16);
                float h1 = __uint_as_float(ph & 0xffff0000u);
                uint32_t pl; PACK_BF16X2(pl, x0 - h0, x1 - h1);
                hv[i] = ph; lv[i] = pl;
            }
            uint32_t off = row * 128 + ((uint32_t)(c8 * 2) ^ ((row & 7) << 4));
            char* dh = isV ? Vh : Kh;
            char* dl = isV ? Vl : Kl;
            *(uint4*)(dh + off) = make_uint4(hv[0], hv[1], hv[2], hv[3]);
            *(uint4*)(dl + off) = make_uint4(lv[0], lv[1], lv[2], lv[3]);
        }
        __syncthreads();

        // ---- S = Q.K^T (split, 3 combos), warp tile 16 x 64 ----
        float s[8][4];
        #pragma unroll
        for (int i = 0; i < 8; i++)
            #pragma unroll
            for (int j = 0; j < 4; j++) s[i][j] = 0.f;

        #pragma unroll
        for (int kc = 0; kc < 4; kc++) {
            uint32_t colb = (uint32_t)(kc * 32 + lhalf);
            uint32_t ah[4], al[4];
            LDSM_X4(ah, sQh + aoff + (colb ^ axor));
            LDSM_X4(al, sQl + aoff + (colb ^ axor));
            #pragma unroll
            for (int gk = 0; gk < 4; gk++) {
                uint32_t ro = (uint32_t)((gk * 16 + lrow) * 128);
                uint32_t kh[4], kl[4];
                LDSM_X4(kh, sKh + ro + (colb ^ kxor));
                LDSM_X4(kl, sKl + ro + (colb ^ kxor));
                #pragma unroll
                for (int pp = 0; pp < 2; pp++) {
                    int nt = gk * 2 + pp;
                    MMA_BF16(s[nt], ah, kh[pp], kh[pp + 2]);
                    MMA_BF16(s[nt], ah, kl[pp], kl[pp + 2]);
                    MMA_BF16(s[nt], al, kh[pp], kh[pp + 2]);
                }
            }
        }

        // ---- causal mask (only when tile overlaps the diagonal) ----
        if (k0 + 63 > qw) {
            int r0 = qw + g, r1 = qw + g + 8;
            #pragma unroll
            for (int nt = 0; nt < 8; nt++) {
                int col = k0 + nt * 8 + 2 * t;
                if (col     > r0) s[nt][0] = -1e30f;
                if (col + 1 > r0) s[nt][1] = -1e30f;
                if (col     > r1) s[nt][2] = -1e30f;
                if (col + 1 > r1) s[nt][3] = -1e30f;
            }
        }

        // ---- online softmax (rows owned by 4 lanes sharing g) ----
        float mx0 = -1e30f, mx1 = -1e30f;
        #pragma unroll
        for (int nt = 0; nt < 8; nt++) {
            mx0 = fmaxf(mx0, fmaxf(s[nt][0], s[nt][1]));
            mx1 = fmaxf(mx1, fmaxf(s[nt][2], s[nt][3]));
        }
        mx0 = fmaxf(mx0, __shfl_xor_sync(0xffffffffu, mx0, 1));
        mx0 = fmaxf(mx0, __shfl_xor_sync(0xffffffffu, mx0, 2));
        mx1 = fmaxf(mx1, __shfl_xor_sync(0xffffffffu, mx1, 1));
        mx1 = fmaxf(mx1, __shfl_xor_sync(0xffffffffu, mx1, 2));
        float mn0 = fmaxf(m0, mx0), mn1 = fmaxf(m1, mx1);
        float c0 = __expf(m0 - mn0), c1 = __expf(m1 - mn1);
        float sum0 = 0.f, sum1 = 0.f;
        #pragma unroll
        for (int nt = 0; nt < 8; nt++) {
            s[nt][0] = __expf(s[nt][0] - mn0);
            s[nt][1] = __expf(s[nt][1] - mn0);
            s[nt][2] = __expf(s[nt][2] - mn1);
            s[nt][3] = __expf(s[nt][3] - mn1);
            sum0 += s[nt][0] + s[nt][1];
            sum1 += s[nt][2] + s[nt][3];
        }
        sum0 += __shfl_xor_sync(0xffffffffu, sum0, 1);
        sum0 += __shfl_xor_sync(0xffffffffu, sum0, 2);
        sum1 += __shfl_xor_sync(0xffffffffu, sum1, 1);
        sum1 += __shfl_xor_sync(0xffffffffu, sum1, 2);
        l0 = l0 * c0 + sum0; l1 = l1 * c1 + sum1;
        m0 = mn0; m1 = mn1;
        #pragma unroll
        for (int nt = 0; nt < 8; nt++) {
            o[nt][0] *= c0; o[nt][1] *= c0;
            o[nt][2] *= c1; o[nt][3] *= c1;
        }

        // ---- pack P into A-fragments (hi/lo split), direct from S regs ----
        uint32_t ph[16], pl[16];
        #pragma unroll
        for (int c2 = 0; c2 < 8; c2++) {
            int ib = (c2 >> 1) * 4 + (c2 & 1) * 2;
            uint32_t p01, p23;
            PACK_BF16X2(p01, s[c2][0], s[c2][1]);
            PACK_BF16X2(p23, s[c2][2], s[c2][3]);
            float h0 = __uint_as_float(p01 << 16);
            float h1 = __uint_as_float(p01 & 0xffff0000u);
            float h2 = __uint_as_float(p23 << 16);
            float h3 = __uint_as_float(p23 & 0xffff0000u);
            uint32_t q01, q23;
            PACK_BF16X2(q01, s[c2][0] - h0, s[c2][1] - h1);
            PACK_BF16X2(q23, s[c2][2] - h2, s[c2][3] - h3);
            ph[ib] = p01; ph[ib + 1] = p23;
            pl[ib] = q01; pl[ib + 1] = q23;
        }

        // ---- O += P.V (split, 3 combos), contraction over 64 keys ----
        #pragma unroll
        for (int kc = 0; kc < 4; kc++) {
            const uint32_t* aH = &ph[kc * 4];
            const uint32_t* aL = &pl[kc * 4];
            uint32_t ro = (uint32_t)((kc * 16 + lrow) * 128);
            #pragma unroll
            for (int j = 0; j < 4; j++) {
                uint32_t cb = ((uint32_t)(j * 32 + lhalf)) ^ kxor;
                uint32_t vh[4], vl[4];
                LDSM_X4_T(vh, sVh + ro + cb);
                LDSM_X4_T(vl, sVl + ro + cb);
                MMA_BF16(o[2*j],     aH, vh[0], vh[1]);
                MMA_BF16(o[2*j + 1], aH, vh[2], vh[3]);
                MMA_BF16(o[2*j],     aH, vl[0], vl[1]);
                MMA_BF16(o[2*j + 1], aH, vl[2], vl[3]);
                MMA_BF16(o[2*j],     aL, vh[0], vh[1]);
                MMA_BF16(o[2*j + 1], aL, vh[2], vh[3]);
            }
        }
    }

    // ---- finalize: O /= l, write fp32 [B,T,C] ----
    float inv0 = 1.0f / l0, inv1 = 1.0f / l1;
    int r0 = qw + g, r1 = qw + g + 8;
    float* ob = out + (size_t)(b * TSEQ) * 1024 + h * 64;
    #pragma unroll
    for (int nt = 0; nt < 8; nt++) {
        int col = nt * 8 + 2 * t;
        float2 v0 = {o[nt][0] * inv0, o[nt][1] * inv0};
        float2 v1 = {o[nt][2] * inv1, o[nt][3] * inv1};
        *(float2*)&ob[(size_t)r0 * 1024 + col] = v0;
        *(float2*)&ob[(size_t)r1 * 1024 + col] = v1;
    }
}

// ---------------------------------------------------------------------------
// Launch
// ---------------------------------------------------------------------------
extern "C" void kernel_launch(void* const* d_in, const int* in_sizes, int n_in,
                              void* d_out, int out_size)
{
    const float* x      = (const float*)d_in[0];
    const float* W_qkv  = (const float*)d_in[1];
    const float* b_qkv  = (const float*)d_in[2];
    const float* W_proj = (const float*)d_in[3];
    const float* b_proj = (const float*)d_in[4];
    float* out = (float*)d_out;

    float *qkv, *att;
    __nv_bfloat16 *xs, *as, *wqs, *wps;
    cudaGetSymbolAddress((void**)&qkv, g_qkv);
    cudaGetSymbolAddress((void**)&att, g_att);
    cudaGetSymbolAddress((void**)&xs,  g_xs);
    cudaGetSymbolAddress((void**)&as,  g_as);
    cudaGetSymbolAddress((void**)&wqs, g_wqs);
    cudaGetSymbolAddress((void**)&wps, g_wps);

    cudaFuncSetAttribute(gemm_bf16_kernel,
                         cudaFuncAttributeMaxDynamicSharedMemorySize, GEMM_SMEM);
    cudaFuncSetAttribute(flash_hmma_kernel,
                         cudaFuncAttributeMaxDynamicSharedMemorySize, FLASH_SMEM);

    // Splits: A operands [hi|hi|lo], B operands [hi|lo|hi]
    split_kernel<<<BT * CDIM / 8 / 256, 256>>>(x, xs, CDIM, 2 * CDIM);
    split_kernel<<<3 * CDIM * CDIM / 8 / 256, 256>>>(W_qkv, wqs, 2 * CDIM, CDIM);
    split_kernel<<<CDIM * CDIM / 8 / 256, 256>>>(W_proj, wps, 2 * CDIM, CDIM);

    // 1) QKV projection (tensor cores, split-K')
    gemm_bf16_kernel<<<dim3(3 * CDIM / 128, BT / 128), 256, GEMM_SMEM>>>(
        xs, wqs, b_qkv, qkv, BT, 3 * CDIM, K3);

    // 2) Causal flash attention (HMMA, split)
    flash_hmma_kernel<<<dim3(TSEQ / 128, NH, BATCH), 256, FLASH_SMEM>>>(qkv, att);

    // 3) Output projection
    split_kernel<<<BT * CDIM / 8 / 256, 256>>>(att, as, CDIM, 2 * CDIM);
    gemm_bf16_kernel<<<dim3(CDIM / 128, BT / 128), 256, GEMM_SMEM>>>(
        as, wps, b_proj, out, BT, CDIM, K3);
}

// round 6
// speedup vs baseline: 3.1749x; 1.2578x over previous
#include <cuda_runtime.h>
#include <cuda_bf16.h>
#include <cstdint>
#include <math.h>

#define BATCH 4
#define TSEQ  2048
#define CDIM  1024
#define NH    16
#define HD    64
#define BT    (BATCH * TSEQ)
#define K3    (3 * CDIM)          // split-extended K dimension = 3072
#define NKT   (TSEQ / 64)         // 32 key tiles per (b,h)

// ---------------------------------------------------------------------------
// Scratch (__device__ globals; no allocation allowed)
// ---------------------------------------------------------------------------
__device__ float g_qkv[(size_t)BT * 3 * CDIM];             // [B*T, 3C] fp32
__device__ float g_att[(size_t)BT * CDIM];                 // [B*T, C]  fp32
__device__ __nv_bfloat16 g_xs[(size_t)BT * K3];            // x split  [hi|hi|lo]
__device__ __nv_bfloat16 g_as[(size_t)BT * K3];            // att split[hi|hi|lo]
__device__ __nv_bfloat16 g_wqs[(size_t)3 * CDIM * K3];     // W_qkv    [hi|lo|hi]
__device__ __nv_bfloat16 g_wps[(size_t)CDIM * K3];         // W_proj   [hi|lo|hi]
// Pre-split K/V: per (b,h,kt) 16KB block = [hi 8KB | lo 8KB], smem-layout bytes
__device__ char g_ksp[(size_t)BATCH * NH * NKT * 16384];
__device__ char g_vsp[(size_t)BATCH * NH * NKT * 16384];

// ---------------------------------------------------------------------------
// PTX helpers (sm_100-baseline safe: cp.async + ldmatrix + mma.sync only)
// ---------------------------------------------------------------------------
__device__ __forceinline__ uint32_t smem_u32(const void* p) {
    uint32_t a;
    asm("{ .reg .u64 t; cvta.to.shared.u64 t, %1; cvt.u32.u64 %0, t; }"
        : "=r"(a) : "l"(p));
    return a;
}

#define CPASYNC16(dst, src) \
    asm volatile("cp.async.cg.shared.global [%0], [%1], 16;" \
        :: "r"(dst), "l"(src))
#define CPASYNC_COMMIT() asm volatile("cp.async.commit_group;")
#define CPASYNC_WAIT1()  asm volatile("cp.async.wait_group 1;")

#define LDSM_X4(r, addr) \
    asm volatile("ldmatrix.sync.aligned.m8n8.x4.shared.b16 {%0,%1,%2,%3}, [%4];" \
        : "=r"((r)[0]), "=r"((r)[1]), "=r"((r)[2]), "=r"((r)[3]) : "r"(addr))

#define LDSM_X4_T(r, addr) \
    asm volatile("ldmatrix.sync.aligned.m8n8.x4.trans.shared.b16 {%0,%1,%2,%3}, [%4];" \
        : "=r"((r)[0]), "=r"((r)[1]), "=r"((r)[2]), "=r"((r)[3]) : "r"(addr))

#define MMA_BF16(d, a, br0, br1) \
    asm volatile("mma.sync.aligned.m16n8k16.row.col.f32.bf16.bf16.f32 " \
        "{%0,%1,%2,%3}, {%4,%5,%6,%7}, {%8,%9}, {%0,%1,%2,%3};" \
        : "+f"((d)[0]), "+f"((d)[1]), "+f"((d)[2]), "+f"((d)[3]) \
        : "r"((a)[0]), "r"((a)[1]), "r"((a)[2]), "r"((a)[3]), "r"(br0), "r"(br1))

// pack two f32 -> bf16x2 (lo = x0, hi = x1)
#define PACK_BF16X2(res, x0, x1) \
    asm("cvt.rn.bf16x2.f32 %0, %1, %2;" : "=r"(res) : "f"(x1), "f"(x0))

// ---------------------------------------------------------------------------
// Split fp32 [R, 1024] -> bf16 [R, 3072]:
// A operand: hi @0, hi @1024, lo @2048   -> A' = [hi|hi|lo]
// B operand: hi @0, lo @1024, hi @2048   -> B' = [hi|lo|hi]
// A'.B'^T = hi.hi + hi.lo + lo.hi  (lo.lo term ~2^-18, dropped)
// ---------------------------------------------------------------------------
__global__ __launch_bounds__(256) void split_kernel(
    const float* __restrict__ src, __nv_bfloat16* __restrict__ dst,
    int hi2_off, int lo_off)
{
    int idx = blockIdx.x * blockDim.x + threadIdx.x;
    int row = idx >> 7;            // K/8 = 128 chunks per row
    int c8  = (idx & 127) << 3;

    const float* p = src + (size_t)row * CDIM + c8;
    float4 v0 = *(const float4*)p;
    float4 v1 = *(const float4*)(p + 4);
    float xs[8] = {v0.x, v0.y, v0.z, v0.w, v1.x, v1.y, v1.z, v1.w};

    uint32_t hv[4], lv[4];
    #pragma unroll
    for (int i = 0; i < 4; i++) {
        float x0 = xs[2*i], x1 = xs[2*i + 1];
        uint32_t ph; PACK_BF16X2(ph, x0, x1);
        float h0 = __uint_as_float(ph << 16);
        float h1 = __uint_as_float(ph & 0xffff0000u);
        uint32_t pl; PACK_BF16X2(pl, x0 - h0, x1 - h1);
        hv[i] = ph; lv[i] = pl;
    }
    uint4 hq = make_uint4(hv[0], hv[1], hv[2], hv[3]);
    uint4 lq = make_uint4(lv[0], lv[1], lv[2], lv[3]);

    __nv_bfloat16* base = dst + (size_t)row * K3;
    *reinterpret_cast<uint4*>(base + c8)           = hq;
    *reinterpret_cast<uint4*>(base + hi2_off + c8) = hq;
    *reinterpret_cast<uint4*>(base + lo_off  + c8) = lq;
}

// ---------------------------------------------------------------------------
// Pre-split K/V tiles into smem-image blocks for verbatim cp.async.
// Block (b,h,kt): 64 rows x 64 cols, row*128B + swizzle, [hi 8KB | lo 8KB].
// ---------------------------------------------------------------------------
__global__ __launch_bounds__(256) void presplit_kv_kernel(
    const float* __restrict__ qkv, char* __restrict__ ksp, char* __restrict__ vsp)
{
    const int tid = threadIdx.x;
    const int kt = blockIdx.x, h = blockIdx.y, b = blockIdx.z;
    size_t blk = ((size_t)((b * NH + h) * NKT + kt)) * 16384;
    char* kh = ksp + blk; char* kl = kh + 8192;
    char* vh = vsp + blk; char* vl = vh + 8192;
    const float* base = qkv + (size_t)(b * TSEQ + kt * 64) * 3072 + h * 64;

    for (int u = tid; u < 1024; u += 256) {
        int isV = u >> 9;
        int uu  = u & 511;
        int row = uu >> 3;
        int c8  = (uu & 7) * 8;
        const float* p = base + (size_t)row * 3072 + (isV ? 2048 : 1024) + c8;
        float4 v0 = *(const float4*)p;
        float4 v1 = *(const float4*)(p + 4);
        float xs[8] = {v0.x, v0.y, v0.z, v0.w, v1.x, v1.y, v1.z, v1.w};
        uint32_t hv[4], lv[4];
        #pragma unroll
        for (int i = 0; i < 4; i++) {
            float x0 = xs[2*i], x1 = xs[2*i + 1];
            uint32_t ph; PACK_BF16X2(ph, x0, x1);
            float h0 = __uint_as_float(ph << 16);
            float h1 = __uint_as_float(ph & 0xffff0000u);
            uint32_t pl; PACK_BF16X2(pl, x0 - h0, x1 - h1);
            hv[i] = ph; lv[i] = pl;
        }
        uint32_t off = row * 128 + ((uint32_t)(c8 * 2) ^ ((row & 7) << 4));
        char* dh = isV ? vh : kh;
        char* dl = isV ? vl : kl;
        *(uint4*)(dh + off) = make_uint4(hv[0], hv[1], hv[2], hv[3]);
        *(uint4*)(dl + off) = make_uint4(lv[0], lv[1], lv[2], lv[3]);
    }
}

// ---------------------------------------------------------------------------
// bf16 NT GEMM via mma.sync (HMMA) — unchanged from Round-4/5 passing kernel
// ---------------------------------------------------------------------------
#define GSTAGE 32768           // A 16KB + B 16KB per stage
#define GEMM_SMEM (2 * GSTAGE)

__global__ __launch_bounds__(256) void gemm_bf16_kernel(
    const __nv_bfloat16* __restrict__ A, const __nv_bfloat16* __restrict__ B,
    const float* __restrict__ bias, float* __restrict__ C,
    int M, int N, int K)
{
    extern __shared__ char sm[];
    uint32_t smb = smem_u32(sm);
    const int tid  = threadIdx.x;
    const int lane = tid & 31;
    const int wid  = tid >> 5;
    const int wm   = wid >> 2;
    const int wn   = wid & 3;
    const int m0   = blockIdx.y * 128;
    const int n0   = blockIdx.x * 128;
    const int NK   = K >> 6;

    const size_t Kb = (size_t)K * 2;
    const char* Abase = (const char*)A + (size_t)m0 * Kb;
    const char* Bbase = (const char*)B + (size_t)n0 * Kb;

    const int lr = tid >> 3;
    const int lc = (tid & 7) << 4;

    float acc[4][4][4];
    #pragma unroll
    for (int i = 0; i < 4; i++)
        #pragma unroll
        for (int j = 0; j < 4; j++)
            #pragma unroll
            for (int r = 0; r < 4; r++) acc[i][j][r] = 0.f;

    const int lrow  = lane & 15;
    const int lhalf = (lane >> 4) << 4;
    uint32_t arow[4], axor[4], brow[2], bxor[2];
    #pragma unroll
    for (int mi = 0; mi < 4; mi++) {
        int r = wm * 64 + mi * 16 + lrow;
        arow[mi] = r * 128; axor[mi] = (r & 7) << 4;
    }
    #pragma unroll
    for (int bi = 0; bi < 2; bi++) {
        int r = wn * 32 + bi * 16 + lrow;
        brow[bi] = r * 128; bxor[bi] = (r & 7) << 4;
    }

    auto load_stage = [&](int kt, int s) {
        uint32_t sa = smb + s * GSTAGE;
        uint32_t sb = sa + 16384;
        size_t ktb = (size_t)kt << 7;
        #pragma unroll
        for (int p = 0; p < 4; p++) {
            int row = lr + p * 32;
            uint32_t so = row * 128 + (lc ^ ((row & 7) << 4));
            CPASYNC16(sa + so, Abase + (size_t)row * Kb + ktb + lc);
            CPASYNC16(sb + so, Bbase + (size_t)row * Kb + ktb + lc);
        }
    };

    load_stage(0, 0); CPASYNC_COMMIT();
    load_stage(1, 1); CPASYNC_COMMIT();

    for (int kt = 0; kt < NK; kt++) {
        CPASYNC_WAIT1();
        __syncthreads();
        uint32_t sa = smb + (kt & 1) * GSTAGE;
        uint32_t sb = sa + 16384;

        #pragma unroll
        for (int ks = 0; ks < 4; ks++) {
            uint32_t kb = (ks << 5) + lhalf;
            uint32_t a[4][4], b[2][4];
            #pragma unroll
            for (int mi = 0; mi < 4; mi++)
                LDSM_X4(a[mi], sa + arow[mi] + (kb ^ axor[mi]));
            #pragma unroll
            for (int bi = 0; bi < 2; bi++)
                LDSM_X4(b[bi], sb + brow[bi] + (kb ^ bxor[bi]));
            #pragma unroll
            for (int mi = 0; mi < 4; mi++)
                #pragma unroll
                for (int ni = 0; ni < 4; ni++)
                    MMA_BF16(acc[mi][ni], a[mi],
                             b[ni >> 1][ni & 1], b[ni >> 1][(ni & 1) + 2]);
        }
        __syncthreads();
        if (kt + 2 < NK) load_stage(kt + 2, kt & 1);
        CPASYNC_COMMIT();
    }

    const int g  = lane >> 2;
    const int tg = (lane & 3) << 1;
    #pragma unroll
    for (int mi = 0; mi < 4; mi++) {
        int r0 = m0 + wm * 64 + mi * 16 + g;
        #pragma unroll
        for (int ni = 0; ni < 4; ni++) {
            int col = n0 + wn * 32 + ni * 8 + tg;
            float b0 = bias[col], b1 = bias[col + 1];
            float2 v0 = {acc[mi][ni][0] + b0, acc[mi][ni][1] + b1};
            float2 v1 = {acc[mi][ni][2] + b0, acc[mi][ni][3] + b1};
            *(float2*)&C[(size_t)r0 * N + col] = v0;
            *(float2*)&C[(size_t)(r0 + 8) * N + col] = v1;
        }
    }
}

// ---------------------------------------------------------------------------
// Flash attention via HMMA, bf16 hi/lo split, causal. V2:
// K/V pre-split in GMEM (smem-image blocks) -> double-buffered cp.async,
// zero in-loop conversion. CTA = 128 queries (8 warps x 16 rows), 64-key tiles.
// smem: Qh/Ql 16KB each + 2 stages x [Kh|Kl|Vh|Vl] 32KB = 96KB.
// ---------------------------------------------------------------------------
#define FSTG 32768
#define FLASH_SMEM (32768 + 2 * FSTG)   // 98304

__global__ __launch_bounds__(256, 1) void flash_hmma_kernel(
    const float* __restrict__ qkv,
    const char* __restrict__ ksp, const char* __restrict__ vsp,
    float* __restrict__ out)
{
    extern __shared__ char sm[];
    uint32_t smb = smem_u32(sm);
    const uint32_t sQh = smb;
    const uint32_t sQl = smb + 16384;
    char* Qh = sm;
    char* Ql = sm + 16384;

    const int tid  = threadIdx.x;
    const int lane = tid & 31;
    const int w    = tid >> 5;
    const int g    = lane >> 2;
    const int t    = lane & 3;
    const int qt   = (gridDim.x - 1) - blockIdx.x;   // heavy tiles first
    const int h    = blockIdx.y;
    const int b    = blockIdx.z;
    const int q0   = qt * 128;

    const float* qbase = qkv + (size_t)(b * TSEQ) * 3072 + h * 64;
    const char* kbh = ksp + ((size_t)((b * NH + h) * NKT)) * 16384;
    const char* vbh = vsp + ((size_t)((b * NH + h) * NKT)) * 16384;

    const int nkt = 2 * qt + 2;

    // ---- K/V stage loader: verbatim 16KB+16KB cp.async ----
    auto load_stage = [&](int kt2, int s) {
        uint32_t d = smb + 32768 + s * FSTG;
        const char* sk = kbh + (size_t)kt2 * 16384;
        const char* sv = vbh + (size_t)kt2 * 16384;
        #pragma unroll
        for (int i = 0; i < 4; i++) {
            uint32_t o = (uint32_t)(tid + i * 256) * 16;
            CPASYNC16(d + o, sk + o);
            CPASYNC16(d + 16384 + o, sv + o);
        }
    };

    load_stage(0, 0); CPASYNC_COMMIT();
    if (nkt > 1) load_stage(1, 1);
    CPASYNC_COMMIT();

    // ---- Load Q tile (128 x 64 fp32), scale by 0.125, split hi/lo to smem ----
    for (int u = tid; u < 1024; u += 256) {
        int row = u >> 3;
        int c8  = (u & 7) * 8;
        const float* p = qbase + (size_t)(q0 + row) * 3072 + c8;
        float4 v0 = *(const float4*)p;
        float4 v1 = *(const float4*)(p + 4);
        float xs[8] = {v0.x, v0.y, v0.z, v0.w, v1.x, v1.y, v1.z, v1.w};
        uint32_t hv[4], lv[4];
        #pragma unroll
        for (int i = 0; i < 4; i++) {
            float x0 = xs[2*i] * 0.125f, x1 = xs[2*i + 1] * 0.125f;
            uint32_t ph; PACK_BF16X2(ph, x0, x1);
            float h0 = __uint_as_float(ph << 16);
            float h1 = __uint_as_float(ph & 0xffff0000u);
            uint32_t pl; PACK_BF16X2(pl, x0 - h0, x1 - h1);
            hv[i] = ph; lv[i] = pl;
        }
        uint32_t off = row * 128 + ((uint32_t)(c8 * 2) ^ ((row & 7) << 4));
        *(uint4*)(Qh + off) = make_uint4(hv[0], hv[1], hv[2], hv[3]);
        *(uint4*)(Ql + off) = make_uint4(lv[0], lv[1], lv[2], lv[3]);
    }

    // ---- per-warp ldmatrix addressing ----
    const int lrow  = lane & 15;
    const int lhalf = (lane >> 4) << 4;
    const uint32_t aoff = (uint32_t)((w * 16 + lrow) * 128);
    const uint32_t axor = (uint32_t)((lrow & 7) << 4);
    const uint32_t kxor = axor;

    // ---- accumulators ----
    float o[8][4];
    #pragma unroll
    for (int i = 0; i < 8; i++)
        #pragma unroll
        for (int j = 0; j < 4; j++) o[i][j] = 0.f;
    float m0 = -1e30f, m1 = -1e30f, l0 = 0.f, l1 = 0.f;
    const int qw = q0 + w * 16;     // warp's first query row

    for (int kt = 0; kt < nkt; kt++) {
        const int k0 = kt * 64;
        CPASYNC_WAIT1();
        __syncthreads();
        const uint32_t sKh = smb + 32768 + (kt & 1) * FSTG;
        const uint32_t sKl = sKh + 8192;
        const uint32_t sVh = sKh + 16384;
        const uint32_t sVl = sKh + 24576;

        // ---- S = Q.K^T (split, 3 combos), warp tile 16 x 64 ----
        float s[8][4];
        #pragma unroll
        for (int i = 0; i < 8; i++)
            #pragma unroll
            for (int j = 0; j < 4; j++) s[i][j] = 0.f;

        #pragma unroll
        for (int kc = 0; kc < 4; kc++) {
            uint32_t colb = (uint32_t)(kc * 32 + lhalf);
            uint32_t ah[4], al[4];
            LDSM_X4(ah, sQh + aoff + (colb ^ axor));
            LDSM_X4(al, sQl + aoff + (colb ^ axor));
            #pragma unroll
            for (int gk = 0; gk < 4; gk++) {
                uint32_t ro = (uint32_t)((gk * 16 + lrow) * 128);
                uint32_t kh[4], kl[4];
                LDSM_X4(kh, sKh + ro + (colb ^ kxor));
                LDSM_X4(kl, sKl + ro + (colb ^ kxor));
                #pragma unroll
                for (int pp = 0; pp < 2; pp++) {
                    int nt = gk * 2 + pp;
                    MMA_BF16(s[nt], ah, kh[pp], kh[pp + 2]);
                    MMA_BF16(s[nt], ah, kl[pp], kl[pp + 2]);
                    MMA_BF16(s[nt], al, kh[pp], kh[pp + 2]);
                }
            }
        }

        // ---- causal mask (only when tile overlaps the diagonal) ----
        if (k0 + 63 > qw) {
            int r0 = qw + g, r1 = qw + g + 8;
            #pragma unroll
            for (int nt = 0; nt < 8; nt++) {
                int col = k0 + nt * 8 + 2 * t;
                if (col     > r0) s[nt][0] = -1e30f;
                if (col + 1 > r0) s[nt][1] = -1e30f;
                if (col     > r1) s[nt][2] = -1e30f;
                if (col + 1 > r1) s[nt][3] = -1e30f;
            }
        }

        // ---- online softmax (rows owned by 4 lanes sharing g) ----
        float mx0 = -1e30f, mx1 = -1e30f;
        #pragma unroll
        for (int nt = 0; nt < 8; nt++) {
            mx0 = fmaxf(mx0, fmaxf(s[nt][0], s[nt][1]));
            mx1 = fmaxf(mx1, fmaxf(s[nt][2], s[nt][3]));
        }
        mx0 = fmaxf(mx0, __shfl_xor_sync(0xffffffffu, mx0, 1));
        mx0 = fmaxf(mx0, __shfl_xor_sync(0xffffffffu, mx0, 2));
        mx1 = fmaxf(mx1, __shfl_xor_sync(0xffffffffu, mx1, 1));
        mx1 = fmaxf(mx1, __shfl_xor_sync(0xffffffffu, mx1, 2));
        float mn0 = fmaxf(m0, mx0), mn1 = fmaxf(m1, mx1);
        float c0 = __expf(m0 - mn0), c1 = __expf(m1 - mn1);
        float sum0 = 0.f, sum1 = 0.f;
        #pragma unroll
        for (int nt = 0; nt < 8; nt++) {
            s[nt][0] = __expf(s[nt][0] - mn0);
            s[nt][1] = __expf(s[nt][1] - mn0);
            s[nt][2] = __expf(s[nt][2] - mn1);
            s[nt][3] = __expf(s[nt][3] - mn1);
            sum0 += s[nt][0] + s[nt][1];
            sum1 += s[nt][2] + s[nt][3];
        }
        sum0 += __shfl_xor_sync(0xffffffffu, sum0, 1);
        sum0 += __shfl_xor_sync(0xffffffffu, sum0, 2);
        sum1 += __shfl_xor_sync(0xffffffffu, sum1, 1);
        sum1 += __shfl_xor_sync(0xffffffffu, sum1, 2);
        l0 = l0 * c0 + sum0; l1 = l1 * c1 + sum1;
        m0 = mn0; m1 = mn1;
        #pragma unroll
        for (int nt = 0; nt < 8; nt++) {
            o[nt][0] *= c0; o[nt][1] *= c0;
            o[nt][2] *= c1; o[nt][3] *= c1;
        }

        // ---- pack P into A-fragments (hi/lo split), direct from S regs ----
        uint32_t ph[16], pl[16];
        #pragma unroll
        for (int c2 = 0; c2 < 8; c2++) {
            int ib = (c2 >> 1) * 4 + (c2 & 1) * 2;
            uint32_t p01, p23;
            PACK_BF16X2(p01, s[c2][0], s[c2][1]);
            PACK_BF16X2(p23, s[c2][2], s[c2][3]);
            float h0 = __uint_as_float(p01 << 16);
            float h1 = __uint_as_float(p01 & 0xffff0000u);
            float h2 = __uint_as_float(p23 << 16);
            float h3 = __uint_as_float(p23 & 0xffff0000u);
            uint32_t q01, q23;
            PACK_BF16X2(q01, s[c2][0] - h0, s[c2][1] - h1);
            PACK_BF16X2(q23, s[c2][2] - h2, s[c2][3] - h3);
            ph[ib] = p01; ph[ib + 1] = p23;
            pl[ib] = q01; pl[ib + 1] = q23;
        }

        // ---- O += P.V (split, 3 combos), contraction over 64 keys ----
        #pragma unroll
        for (int kc = 0; kc < 4; kc++) {
            const uint32_t* aH = &ph[kc * 4];
            const uint32_t* aL = &pl[kc * 4];
            uint32_t ro = (uint32_t)((kc * 16 + lrow) * 128);
            #pragma unroll
            for (int j = 0; j < 4; j++) {
                uint32_t cb = ((uint32_t)(j * 32 + lhalf)) ^ kxor;
                uint32_t vh[4], vl[4];
                LDSM_X4_T(vh, sVh + ro + cb);
                LDSM_X4_T(vl, sVl + ro + cb);
                MMA_BF16(o[2*j],     aH, vh[0], vh[1]);
                MMA_BF16(o[2*j + 1], aH, vh[2], vh[3]);
                MMA_BF16(o[2*j],     aH, vl[0], vl[1]);
                MMA_BF16(o[2*j + 1], aH, vl[2], vl[3]);
                MMA_BF16(o[2*j],     aL, vh[0], vh[1]);
                MMA_BF16(o[2*j + 1], aL, vh[2], vh[3]);
            }
        }

        __syncthreads();
        if (kt + 2 < nkt) load_stage(kt + 2, kt & 1);
        CPASYNC_COMMIT();
    }

    // ---- finalize: O /= l, write fp32 [B,T,C] ----
    float inv0 = 1.0f / l0, inv1 = 1.0f / l1;
    int r0 = qw + g, r1 = qw + g + 8;
    float* ob = out + (size_t)(b * TSEQ) * 1024 + h * 64;
    #pragma unroll
    for (int nt = 0; nt < 8; nt++) {
        int col = nt * 8 + 2 * t;
        float2 v0 = {o[nt][0] * inv0, o[nt][1] * inv0};
        float2 v1 = {o[nt][2] * inv1, o[nt][3] * inv1};
        *(float2*)&ob[(size_t)r0 * 1024 + col] = v0;
        *(float2*)&ob[(size_t)r1 * 1024 + col] = v1;
    }
}

// ---------------------------------------------------------------------------
// Launch
// ---------------------------------------------------------------------------
extern "C" void kernel_launch(void* const* d_in, const int* in_sizes, int n_in,
                              void* d_out, int out_size)
{
    const float* x      = (const float*)d_in[0];
    const float* W_qkv  = (const float*)d_in[1];
    const float* b_qkv  = (const float*)d_in[2];
    const float* W_proj = (const float*)d_in[3];
    const float* b_proj = (const float*)d_in[4];
    float* out = (float*)d_out;

    float *qkv, *att;
    __nv_bfloat16 *xs, *as, *wqs, *wps;
    char *ksp, *vsp;
    cudaGetSymbolAddress((void**)&qkv, g_qkv);
    cudaGetSymbolAddress((void**)&att, g_att);
    cudaGetSymbolAddress((void**)&xs,  g_xs);
    cudaGetSymbolAddress((void**)&as,  g_as);
    cudaGetSymbolAddress((void**)&wqs, g_wqs);
    cudaGetSymbolAddress((void**)&wps, g_wps);
    cudaGetSymbolAddress((void**)&ksp, g_ksp);
    cudaGetSymbolAddress((void**)&vsp, g_vsp);

    cudaFuncSetAttribute(gemm_bf16_kernel,
                         cudaFuncAttributeMaxDynamicSharedMemorySize, GEMM_SMEM);
    cudaFuncSetAttribute(flash_hmma_kernel,
                         cudaFuncAttributeMaxDynamicSharedMemorySize, FLASH_SMEM);

    // Splits: A operands [hi|hi|lo], B operands [hi|lo|hi]
    split_kernel<<<BT * CDIM / 8 / 256, 256>>>(x, xs, CDIM, 2 * CDIM);
    split_kernel<<<3 * CDIM * CDIM / 8 / 256, 256>>>(W_qkv, wqs, 2 * CDIM, CDIM);
    split_kernel<<<CDIM * CDIM / 8 / 256, 256>>>(W_proj, wps, 2 * CDIM, CDIM);

    // 1) QKV projection (tensor cores, split-K')
    gemm_bf16_kernel<<<dim3(3 * CDIM / 128, BT / 128), 256, GEMM_SMEM>>>(
        xs, wqs, b_qkv, qkv, BT, 3 * CDIM, K3);

    // 1b) Pre-split K/V into smem-image blocks
    presplit_kv_kernel<<<dim3(NKT, NH, BATCH), 256>>>(qkv, ksp, vsp);

    // 2) Causal flash attention (HMMA, split, cp.async K/V)
    flash_hmma_kernel<<<dim3(TSEQ / 128, NH, BATCH), 256, FLASH_SMEM>>>(
        qkv, ksp, vsp, att);

    // 3) Output projection
    split_kernel<<<BT * CDIM / 8 / 256, 256>>>(att, as, CDIM, 2 * CDIM);
    gemm_bf16_kernel<<<dim3(CDIM / 128, BT / 128), 256, GEMM_SMEM>>>(
        as, wps, b_proj, out, BT, CDIM, K3);
}